// round 1
// baseline (speedup 1.0000x reference)
#include <cuda_runtime.h>
#include <cstdint>

#define BATCH 16
#define RDIM 256
#define CDIM 256
#define NPIX (RDIM*CDIM)
#define F 64
#define M_TOTAL (BATCH*NPIX)   /* 1048576 rows */

// ---------------- scratch (static device allocations are allowed) ------------
__device__ float g_Ht[(size_t)M_TOTAL * F];   // pre-BN linear output, 256MB
__device__ float g_sum[F];
__device__ float g_sumsq[F];
__device__ float g_scale[F];
__device__ float g_bias[F];

// ---------------- helpers ----------------------------------------------------
__device__ __forceinline__ uint32_t f2tf(float x) {
    uint32_t u;
    asm("cvt.rna.tf32.f32 %0, %1;" : "=r"(u) : "f"(x));
    return u;
}

__device__ __forceinline__ float dval(int i, int j) {
    int ri = 3 - (i == 0) - (i == RDIM - 1);
    int rj = 3 - (j == 0) - (j == CDIM - 1);
    return rsqrtf((float)(ri * rj) + 1e-5f);
}

// ---------------- K0: zero stats ---------------------------------------------
__global__ void k_zero() {
    int t = threadIdx.x;
    if (t < F) { g_sum[t] = 0.f; g_sumsq[t] = 0.f; }
}

// ---------------- K1: Ht = H @ W (tf32 mma) + fused channel stats ------------
// CTA: 128 threads (4 warps). Tile: 128 rows x 64 cols. Warp: 32 rows x 64 cols.
#define SHS 68   /* smem stride (padding chosen for conflict-free A-frag loads) */

__global__ __launch_bounds__(128)
void k_gemm(const float* __restrict__ H, const float* __restrict__ W) {
    extern __shared__ float smem[];
    float* sH   = smem;                       // 128*SHS
    float* sW   = smem + 128 * SHS;           // 64*SHS
    float* sSum = sW + 64 * SHS;              // 64
    float* sSq  = sSum + F;                   // 64

    const int tid  = threadIdx.x;
    const int warp = tid >> 5;
    const int lane = tid & 31;
    const int g    = lane >> 2;   // groupID 0..7
    const int tg   = lane & 3;    // threadID in group 0..3
    const size_t m0 = (size_t)blockIdx.x * 128;

    if (tid < F) { sSum[tid] = 0.f; sSq[tid] = 0.f; }

    // Load W (64x64) -> tf32 in smem
    for (int idx = tid; idx < 64 * 16; idx += 128) {
        int r = idx >> 4, c4 = (idx & 15) * 4;
        float4 v = ((const float4*)W)[idx];
        float4 o;
        o.x = __uint_as_float(f2tf(v.x));
        o.y = __uint_as_float(f2tf(v.y));
        o.z = __uint_as_float(f2tf(v.z));
        o.w = __uint_as_float(f2tf(v.w));
        *(float4*)&sW[r * SHS + c4] = o;
    }
    // Load H tile (128x64) -> tf32 in smem
    const float4* Hp = (const float4*)(H + m0 * F);
    for (int idx = tid; idx < 128 * 16; idx += 128) {
        int r = idx >> 4, c4 = (idx & 15) * 4;
        float4 v = Hp[idx];
        float4 o;
        o.x = __uint_as_float(f2tf(v.x));
        o.y = __uint_as_float(f2tf(v.y));
        o.z = __uint_as_float(f2tf(v.z));
        o.w = __uint_as_float(f2tf(v.w));
        *(float4*)&sH[r * SHS + c4] = o;
    }
    __syncthreads();

    float acc[2][8][4];
#pragma unroll
    for (int mt = 0; mt < 2; mt++)
#pragma unroll
        for (int nt = 0; nt < 8; nt++)
#pragma unroll
            for (int i = 0; i < 4; i++) acc[mt][nt][i] = 0.f;

    const int mrow = warp * 32;

#pragma unroll
    for (int kk = 0; kk < 8; kk++) {
        const int k0 = kk * 8;
        uint32_t a[2][4];
#pragma unroll
        for (int mt = 0; mt < 2; mt++) {
            int rb = mrow + mt * 16;
            a[mt][0] = __float_as_uint(sH[(rb + g    ) * SHS + k0 + tg    ]);
            a[mt][1] = __float_as_uint(sH[(rb + g + 8) * SHS + k0 + tg    ]);
            a[mt][2] = __float_as_uint(sH[(rb + g    ) * SHS + k0 + tg + 4]);
            a[mt][3] = __float_as_uint(sH[(rb + g + 8) * SHS + k0 + tg + 4]);
        }
#pragma unroll
        for (int nt = 0; nt < 8; nt++) {
            uint32_t b0 = __float_as_uint(sW[(k0 + tg    ) * SHS + nt * 8 + g]);
            uint32_t b1 = __float_as_uint(sW[(k0 + tg + 4) * SHS + nt * 8 + g]);
#pragma unroll
            for (int mt = 0; mt < 2; mt++) {
                asm volatile(
                    "mma.sync.aligned.m16n8k8.row.col.f32.tf32.tf32.f32 "
                    "{%0,%1,%2,%3}, {%4,%5,%6,%7}, {%8,%9}, {%0,%1,%2,%3};"
                    : "+f"(acc[mt][nt][0]), "+f"(acc[mt][nt][1]),
                      "+f"(acc[mt][nt][2]), "+f"(acc[mt][nt][3])
                    : "r"(a[mt][0]), "r"(a[mt][1]), "r"(a[mt][2]), "r"(a[mt][3]),
                      "r"(b0), "r"(b1));
            }
        }
    }

    // Write Ht + accumulate per-channel stats from register fragments.
    float s[8][2], q[8][2];
#pragma unroll
    for (int nt = 0; nt < 8; nt++) { s[nt][0] = s[nt][1] = q[nt][0] = q[nt][1] = 0.f; }

    float* outp = g_Ht + m0 * F;
#pragma unroll
    for (int mt = 0; mt < 2; mt++) {
        int rb = mrow + mt * 16;
#pragma unroll
        for (int nt = 0; nt < 8; nt++) {
            int colb = nt * 8 + 2 * tg;
            float2 v0 = make_float2(acc[mt][nt][0], acc[mt][nt][1]);
            float2 v1 = make_float2(acc[mt][nt][2], acc[mt][nt][3]);
            *(float2*)&outp[(size_t)(rb + g    ) * F + colb] = v0;
            *(float2*)&outp[(size_t)(rb + g + 8) * F + colb] = v1;
            s[nt][0] += v0.x + v1.x;            s[nt][1] += v0.y + v1.y;
            q[nt][0] += v0.x * v0.x + v1.x * v1.x;
            q[nt][1] += v0.y * v0.y + v1.y * v1.y;
        }
    }
    // Butterfly over the g dimension (lanes sharing tg differ by multiples of 4)
#pragma unroll
    for (int off = 4; off < 32; off <<= 1) {
#pragma unroll
        for (int nt = 0; nt < 8; nt++) {
            s[nt][0] += __shfl_xor_sync(0xffffffffu, s[nt][0], off);
            s[nt][1] += __shfl_xor_sync(0xffffffffu, s[nt][1], off);
            q[nt][0] += __shfl_xor_sync(0xffffffffu, q[nt][0], off);
            q[nt][1] += __shfl_xor_sync(0xffffffffu, q[nt][1], off);
        }
    }
    if (lane < 4) {
#pragma unroll
        for (int nt = 0; nt < 8; nt++) {
            int c = nt * 8 + 2 * lane;
            atomicAdd(&sSum[c],     s[nt][0]);
            atomicAdd(&sSum[c + 1], s[nt][1]);
            atomicAdd(&sSq[c],      q[nt][0]);
            atomicAdd(&sSq[c + 1],  q[nt][1]);
        }
    }
    __syncthreads();
    if (tid < F) {
        atomicAdd(&g_sum[tid],   sSum[tid]);
        atomicAdd(&g_sumsq[tid], sSq[tid]);
    }
}

// ---------------- K2: finalize BN scale/bias ---------------------------------
__global__ void k_stats(const float* __restrict__ gamma, const float* __restrict__ beta) {
    int o = threadIdx.x;
    if (o < F) {
        float inv_m = 1.f / (float)M_TOTAL;
        float mean = g_sum[o] * inv_m;
        float var  = g_sumsq[o] * inv_m - mean * mean;
        float is   = rsqrtf(var + 1e-5f);
        float sc   = gamma[o] * is;
        g_scale[o] = sc;
        g_bias[o]  = beta[o] - mean * sc;
    }
}

// ---------------- K3: BN + ReLU + normalized 3x3 stencil ---------------------
// CTA: 288 threads = 18 cols (16 out + 2 halo) x 16 float4 chunks, 32 rows.
// Rolling 3-row window in registers; per-row column-sum exchange via smem.
__global__ __launch_bounds__(288)
void k_stencil(float* __restrict__ out) {
    __shared__ float4 cs[2][18][16];

    const int tid   = threadIdx.x;
    const int chunk = tid & 15;      // 0..15 (float4 within channel dim)
    const int colL  = tid >> 4;      // 0..17
    const int b     = blockIdx.z;
    const int j0    = blockIdx.x * 16;
    const int i0    = blockIdx.y * 32;
    const int j     = j0 - 1 + colL;
    const bool jin  = (j >= 0 && j < CDIM);
    const bool isOut = (colL >= 1 && colL <= 16);

    const float4 sc = *(const float4*)&g_scale[chunk * 4];
    const float4 bs = *(const float4*)&g_bias[chunk * 4];
    const float* base = g_Ht + (size_t)b * NPIX * F;

    auto loadrow = [&](int i) -> float4 {
        if (!jin || i < 0 || i >= RDIM) return make_float4(0.f, 0.f, 0.f, 0.f);
        float4 v = *(const float4*)&base[((size_t)i * CDIM + j) * F + chunk * 4];
        float d = dval(i, j);
        float4 r;
        r.x = fmaxf(fmaf(v.x, sc.x, bs.x), 0.f) * d;
        r.y = fmaxf(fmaf(v.y, sc.y, bs.y), 0.f) * d;
        r.z = fmaxf(fmaf(v.z, sc.z, bs.z), 0.f) * d;
        r.w = fmaxf(fmaf(v.w, sc.w, bs.w), 0.f) * d;
        return r;
    };

    float4 p = loadrow(i0 - 1);
    float4 c = loadrow(i0);
    int buf = 0;

    for (int r = 0; r < 32; r++) {
        const int i = i0 + r;
        float4 n = loadrow(i + 1);
        float4 v;
        v.x = p.x + c.x + n.x;
        v.y = p.y + c.y + n.y;
        v.z = p.z + c.z + n.z;
        v.w = p.w + c.w + n.w;
        cs[buf][colL][chunk] = v;
        __syncthreads();
        if (isOut) {
            float4 a0 = cs[buf][colL - 1][chunk];
            float4 a2 = cs[buf][colL + 1][chunk];
            float dc = dval(i, j);
            float4 o;
            o.x = (a0.x + v.x + a2.x) * dc;
            o.y = (a0.y + v.y + a2.y) * dc;
            o.z = (a0.z + v.z + a2.z) * dc;
            o.w = (a0.w + v.w + a2.w) * dc;
            *(float4*)&out[((size_t)b * NPIX + (size_t)i * CDIM + j) * F + chunk * 4] = o;
        }
        p = c; c = n; buf ^= 1;
    }
}

// ---------------- launch ------------------------------------------------------
extern "C" void kernel_launch(void* const* d_in, const int* in_sizes, int n_in,
                              void* d_out, int out_size) {
    (void)in_sizes; (void)n_in; (void)out_size;
    const float* H     = (const float*)d_in[0];
    const float* W     = (const float*)d_in[1];
    const float* gamma = (const float*)d_in[2];
    const float* beta  = (const float*)d_in[3];
    float* out = (float*)d_out;

    const int smemK1 = (128 * SHS + 64 * SHS + 2 * F) * sizeof(float);  // ~52.8KB
    cudaFuncSetAttribute(k_gemm, cudaFuncAttributeMaxDynamicSharedMemorySize, smemK1);

    k_zero<<<1, 64>>>();
    k_gemm<<<M_TOTAL / 128, 128, smemK1>>>(H, W);
    k_stats<<<1, 64>>>(gamma, beta);
    dim3 g3(CDIM / 16, RDIM / 32, BATCH);
    k_stencil<<<g3, 288>>>(out);
}

// round 2
// speedup vs baseline: 1.3580x; 1.3580x over previous
#include <cuda_runtime.h>
#include <cuda_fp16.h>
#include <cstdint>

#define BATCH 16
#define RDIM 256
#define CDIM 256
#define NPIX (RDIM*CDIM)
#define F 64
#define M_TOTAL (BATCH*NPIX)   /* 1048576 rows */

// ---------------- scratch ----------------------------------------------------
__device__ __half g_Htp[(size_t)M_TOTAL * F];   // pre-BN linear output, fp16, 128MB
__device__ float g_sum[F];
__device__ float g_sumsq[F];
__device__ float g_scale[F];
__device__ float g_bias[F];

// ---------------- helpers ----------------------------------------------------
__device__ __forceinline__ uint32_t f2tf(float x) {
    uint32_t u;
    asm("cvt.rna.tf32.f32 %0, %1;" : "=r"(u) : "f"(x));
    return u;
}

__device__ __forceinline__ float dval(int i, int j) {
    int ri = 3 - (i == 0) - (i == RDIM - 1);
    int rj = 3 - (j == 0) - (j == CDIM - 1);
    return rsqrtf((float)(ri * rj) + 1e-5f);
}

// ---------------- K0: zero stats ---------------------------------------------
__global__ void k_zero() {
    int t = threadIdx.x;
    if (t < F) { g_sum[t] = 0.f; g_sumsq[t] = 0.f; }
}

// ---------------- K1: Ht = H @ W (tf32 mma) + fused channel stats ------------
// CTA: 128 threads (4 warps), 512 rows (4 tiles of 128). W loaded once.
#define SHS 68   /* smem stride */
#define ROWS_PER_CTA 512

__global__ __launch_bounds__(128)
void k_gemm(const float* __restrict__ H, const float* __restrict__ W) {
    extern __shared__ float smem[];
    float* sW   = smem;                       // 64*SHS
    float* sH   = smem + 64 * SHS;            // 128*SHS
    float* sSum = sH + 128 * SHS;             // 64
    float* sSq  = sSum + F;                   // 64

    const int tid  = threadIdx.x;
    const int warp = tid >> 5;
    const int lane = tid & 31;
    const int g    = lane >> 2;   // groupID 0..7
    const int tg   = lane & 3;    // threadID in group 0..3
    const int mrow = warp * 32;

    if (tid < F) { sSum[tid] = 0.f; sSq[tid] = 0.f; }

    // Load W (64x64) -> tf32 in smem (once per CTA)
    for (int idx = tid; idx < 64 * 16; idx += 128) {
        int r = idx >> 4, c4 = (idx & 15) * 4;
        float4 v = ((const float4*)W)[idx];
        float4 o;
        o.x = __uint_as_float(f2tf(v.x));
        o.y = __uint_as_float(f2tf(v.y));
        o.z = __uint_as_float(f2tf(v.z));
        o.w = __uint_as_float(f2tf(v.w));
        *(float4*)&sW[r * SHS + c4] = o;
    }

    for (int t = 0; t < ROWS_PER_CTA / 128; t++) {
        const size_t m0 = (size_t)blockIdx.x * ROWS_PER_CTA + (size_t)t * 128;

        __syncthreads();   // protect sH from previous tile's readers (and order W load)

        // Load H tile (128x64) -> tf32 in smem
        const float4* Hp = (const float4*)(H + m0 * F);
        for (int idx = tid; idx < 128 * 16; idx += 128) {
            int r = idx >> 4, c4 = (idx & 15) * 4;
            float4 v = Hp[idx];
            float4 o;
            o.x = __uint_as_float(f2tf(v.x));
            o.y = __uint_as_float(f2tf(v.y));
            o.z = __uint_as_float(f2tf(v.z));
            o.w = __uint_as_float(f2tf(v.w));
            *(float4*)&sH[r * SHS + c4] = o;
        }
        __syncthreads();

        float acc[2][8][4];
#pragma unroll
        for (int mt = 0; mt < 2; mt++)
#pragma unroll
            for (int nt = 0; nt < 8; nt++)
#pragma unroll
                for (int i = 0; i < 4; i++) acc[mt][nt][i] = 0.f;

#pragma unroll
        for (int kk = 0; kk < 8; kk++) {
            const int k0 = kk * 8;
            uint32_t a[2][4];
#pragma unroll
            for (int mt = 0; mt < 2; mt++) {
                int rb = mrow + mt * 16;
                a[mt][0] = __float_as_uint(sH[(rb + g    ) * SHS + k0 + tg    ]);
                a[mt][1] = __float_as_uint(sH[(rb + g + 8) * SHS + k0 + tg    ]);
                a[mt][2] = __float_as_uint(sH[(rb + g    ) * SHS + k0 + tg + 4]);
                a[mt][3] = __float_as_uint(sH[(rb + g + 8) * SHS + k0 + tg + 4]);
            }
#pragma unroll
            for (int nt = 0; nt < 8; nt++) {
                uint32_t b0 = __float_as_uint(sW[(k0 + tg    ) * SHS + nt * 8 + g]);
                uint32_t b1 = __float_as_uint(sW[(k0 + tg + 4) * SHS + nt * 8 + g]);
#pragma unroll
                for (int mt = 0; mt < 2; mt++) {
                    asm volatile(
                        "mma.sync.aligned.m16n8k8.row.col.f32.tf32.tf32.f32 "
                        "{%0,%1,%2,%3}, {%4,%5,%6,%7}, {%8,%9}, {%0,%1,%2,%3};"
                        : "+f"(acc[mt][nt][0]), "+f"(acc[mt][nt][1]),
                          "+f"(acc[mt][nt][2]), "+f"(acc[mt][nt][3])
                        : "r"(a[mt][0]), "r"(a[mt][1]), "r"(a[mt][2]), "r"(a[mt][3]),
                          "r"(b0), "r"(b1));
                }
            }
        }

        // Write Ht (fp16) + per-tile channel stats (short register lifetime).
        float s[8][2], q[8][2];
#pragma unroll
        for (int nt = 0; nt < 8; nt++) { s[nt][0] = s[nt][1] = q[nt][0] = q[nt][1] = 0.f; }

        __half* outp = g_Htp + m0 * F;
#pragma unroll
        for (int mt = 0; mt < 2; mt++) {
            int rb = mrow + mt * 16;
#pragma unroll
            for (int nt = 0; nt < 8; nt++) {
                int colb = nt * 8 + 2 * tg;
                float a0 = acc[mt][nt][0], a1 = acc[mt][nt][1];
                float a2 = acc[mt][nt][2], a3 = acc[mt][nt][3];
                *(__half2*)&outp[(size_t)(rb + g    ) * F + colb] = __floats2half2_rn(a0, a1);
                *(__half2*)&outp[(size_t)(rb + g + 8) * F + colb] = __floats2half2_rn(a2, a3);
                s[nt][0] += a0 + a2;           s[nt][1] += a1 + a3;
                q[nt][0] += a0 * a0 + a2 * a2; q[nt][1] += a1 * a1 + a3 * a3;
            }
        }
        // Butterfly over g (lanes sharing tg differ by multiples of 4)
#pragma unroll
        for (int off = 4; off < 32; off <<= 1) {
#pragma unroll
            for (int nt = 0; nt < 8; nt++) {
                s[nt][0] += __shfl_xor_sync(0xffffffffu, s[nt][0], off);
                s[nt][1] += __shfl_xor_sync(0xffffffffu, s[nt][1], off);
                q[nt][0] += __shfl_xor_sync(0xffffffffu, q[nt][0], off);
                q[nt][1] += __shfl_xor_sync(0xffffffffu, q[nt][1], off);
            }
        }
        if (lane < 4) {
#pragma unroll
            for (int nt = 0; nt < 8; nt++) {
                int c = nt * 8 + 2 * lane;
                atomicAdd(&sSum[c],     s[nt][0]);
                atomicAdd(&sSum[c + 1], s[nt][1]);
                atomicAdd(&sSq[c],      q[nt][0]);
                atomicAdd(&sSq[c + 1],  q[nt][1]);
            }
        }
    }

    __syncthreads();
    if (tid < F) {
        atomicAdd(&g_sum[tid],   sSum[tid]);
        atomicAdd(&g_sumsq[tid], sSq[tid]);
    }
}

// ---------------- K2: finalize BN scale/bias ---------------------------------
__global__ void k_stats(const float* __restrict__ gamma, const float* __restrict__ beta) {
    int o = threadIdx.x;
    if (o < F) {
        float inv_m = 1.f / (float)M_TOTAL;
        float mean = g_sum[o] * inv_m;
        float var  = g_sumsq[o] * inv_m - mean * mean;
        float is   = rsqrtf(var + 1e-5f);
        float sc   = gamma[o] * is;
        g_scale[o] = sc;
        g_bias[o]  = beta[o] - mean * sc;
    }
}

// ---------------- K3: BN + ReLU + normalized 3x3 stencil (fp16 in) -----------
// CTA: 288 threads = 18 cols (16 out + 2 halo) x 16 half4 chunks, 32 rows.
// Rolling 3-row window; raw load software-pipelined one iteration ahead.
__global__ __launch_bounds__(288)
void k_stencil(float* __restrict__ out) {
    __shared__ float4 cs[2][18][16];

    const int tid   = threadIdx.x;
    const int chunk = tid & 15;      // 0..15 (4 channels each)
    const int colL  = tid >> 4;      // 0..17
    const int b     = blockIdx.z;
    const int j0    = blockIdx.x * 16;
    const int i0    = blockIdx.y * 32;
    const int j     = j0 - 1 + colL;
    const bool jin  = (j >= 0 && j < CDIM);
    const bool isOut = (colL >= 1 && colL <= 16);

    const float4 sc = *(const float4*)&g_scale[chunk * 4];
    const float4 bs = *(const float4*)&g_bias[chunk * 4];
    const __half* base = g_Htp + (size_t)b * NPIX * F;

    auto rawload = [&](int i) -> uint2 {
        if (!jin || i < 0 || i >= RDIM) return make_uint2(0u, 0u);
        return *(const uint2*)&base[((size_t)i * CDIM + j) * F + chunk * 4];
    };
    auto bnrow = [&](uint2 rw, int i) -> float4 {
        if (!jin || i < 0 || i >= RDIM) return make_float4(0.f, 0.f, 0.f, 0.f);
        float2 f0 = __half22float2(*(__half2*)&rw.x);
        float2 f1 = __half22float2(*(__half2*)&rw.y);
        float d = dval(i, j);
        float4 r;
        r.x = fmaxf(fmaf(f0.x, sc.x, bs.x), 0.f) * d;
        r.y = fmaxf(fmaf(f0.y, sc.y, bs.y), 0.f) * d;
        r.z = fmaxf(fmaf(f1.x, sc.z, bs.z), 0.f) * d;
        r.w = fmaxf(fmaf(f1.y, sc.w, bs.w), 0.f) * d;
        return r;
    };

    float4 p = bnrow(rawload(i0 - 1), i0 - 1);
    float4 c = bnrow(rawload(i0), i0);
    uint2 rn = rawload(i0 + 1);
    int buf = 0;

    for (int r = 0; r < 32; r++) {
        const int i = i0 + r;
        uint2 rn2 = rawload(i + 2);           // issued a full iteration early
        float4 n = bnrow(rn, i + 1);
        float4 v;
        v.x = p.x + c.x + n.x;
        v.y = p.y + c.y + n.y;
        v.z = p.z + c.z + n.z;
        v.w = p.w + c.w + n.w;
        cs[buf][colL][chunk] = v;
        __syncthreads();
        if (isOut) {
            float4 a0 = cs[buf][colL - 1][chunk];
            float4 a2 = cs[buf][colL + 1][chunk];
            float dc = dval(i, j);
            float4 o;
            o.x = (a0.x + v.x + a2.x) * dc;
            o.y = (a0.y + v.y + a2.y) * dc;
            o.z = (a0.z + v.z + a2.z) * dc;
            o.w = (a0.w + v.w + a2.w) * dc;
            *(float4*)&out[((size_t)b * NPIX + (size_t)i * CDIM + j) * F + chunk * 4] = o;
        }
        p = c; c = n; rn = rn2; buf ^= 1;
    }
}

// ---------------- launch ------------------------------------------------------
extern "C" void kernel_launch(void* const* d_in, const int* in_sizes, int n_in,
                              void* d_out, int out_size) {
    (void)in_sizes; (void)n_in; (void)out_size;
    const float* H     = (const float*)d_in[0];
    const float* W     = (const float*)d_in[1];
    const float* gamma = (const float*)d_in[2];
    const float* beta  = (const float*)d_in[3];
    float* out = (float*)d_out;

    const int smemK1 = (64 * SHS + 128 * SHS + 2 * F) * sizeof(float);  // ~52.8KB
    cudaFuncSetAttribute(k_gemm, cudaFuncAttributeMaxDynamicSharedMemorySize, smemK1);

    k_zero<<<1, 64>>>();
    k_gemm<<<M_TOTAL / ROWS_PER_CTA, 128, smemK1>>>(H, W);
    k_stats<<<1, 64>>>(gamma, beta);
    dim3 g3(CDIM / 16, RDIM / 32, BATCH);
    k_stencil<<<g3, 288>>>(out);
}

// round 3
// speedup vs baseline: 1.9503x; 1.4362x over previous
#include <cuda_runtime.h>
#include <cuda_fp16.h>
#include <cstdint>

#define BATCH 16
#define RDIM 256
#define CDIM 256
#define NPIX (RDIM*CDIM)
#define F 64
#define M_TOTAL (BATCH*NPIX)   /* 1048576 rows */

// ---------------- scratch ----------------------------------------------------
__device__ __half g_Htp[(size_t)M_TOTAL * F];   // pre-BN linear output, fp16, 128MB
__device__ float g_sum[F];
__device__ float g_sumsq[F];
__device__ float g_scale[F];
__device__ float g_bias[F];

// ---------------- helpers ----------------------------------------------------
__device__ __forceinline__ uint32_t f2tf(float x) {
    uint32_t u;
    asm("cvt.rna.tf32.f32 %0, %1;" : "=r"(u) : "f"(x));
    return u;
}

__device__ __forceinline__ void cp_async16(void* smem_dst, const void* gsrc) {
    uint32_t s = (uint32_t)__cvta_generic_to_shared(smem_dst);
    asm volatile("cp.async.cg.shared.global [%0], [%1], 16;\n" :: "r"(s), "l"(gsrc));
}

__device__ __forceinline__ float dval(int i, int j) {
    int ri = 3 - (i == 0) - (i == RDIM - 1);
    int rj = 3 - (j == 0) - (j == CDIM - 1);
    return rsqrtf((float)(ri * rj) + 1e-5f);
}

// ---------------- K0: zero stats ---------------------------------------------
__global__ void k_zero() {
    int t = threadIdx.x;
    if (t < F) { g_sum[t] = 0.f; g_sumsq[t] = 0.f; }
}

// ---------------- K1: Ht = H @ W (tf32 mma), cp.async double buffer ----------
// CTA: 128 threads (4 warps). 8 tiles of 128 rows = 1024 rows per CTA.
#define SHS 68
#define TILES_PER_CTA 8
#define ROWS_PER_CTA (TILES_PER_CTA * 128)

__global__ __launch_bounds__(128)
void k_gemm(const float* __restrict__ H, const float* __restrict__ W) {
    extern __shared__ float smem[];
    float* sW   = smem;                        // 64*SHS
    float* sHa  = smem + 64 * SHS;             // 128*SHS (buffer A)
    float* sHb  = sHa + 128 * SHS;             // 128*SHS (buffer B)
    float* sSum = sHb + 128 * SHS;             // 64
    float* sSq  = sSum + F;                    // 64

    const int tid  = threadIdx.x;
    const int warp = tid >> 5;
    const int lane = tid & 31;
    const int g    = lane >> 2;
    const int tg   = lane & 3;
    const int mrow = warp * 32;

    if (tid < F) { sSum[tid] = 0.f; sSq[tid] = 0.f; }

    // Load W (64x64) -> tf32 (rna) in smem, once per CTA
    for (int idx = tid; idx < 64 * 16; idx += 128) {
        int r = idx >> 4, c4 = (idx & 15) * 4;
        float4 v = ((const float4*)W)[idx];
        float4 o;
        o.x = __uint_as_float(f2tf(v.x));
        o.y = __uint_as_float(f2tf(v.y));
        o.z = __uint_as_float(f2tf(v.z));
        o.w = __uint_as_float(f2tf(v.w));
        *(float4*)&sW[r * SHS + c4] = o;
    }

    const float* ctaH = H + (size_t)blockIdx.x * ROWS_PER_CTA * F;

    auto issue_tile = [&](int t, float* buf) {
        const float* src = ctaH + (size_t)t * 128 * F;
#pragma unroll
        for (int k = 0; k < 16; k++) {
            int idx = tid + 128 * k;
            int r = idx >> 4, c4 = (idx & 15) * 4;
            cp_async16(&buf[r * SHS + c4], src + (size_t)idx * 4);
        }
        asm volatile("cp.async.commit_group;\n" ::);
    };

    issue_tile(0, sHa);

    // Cross-tile stat accumulators (registers)
    float s[8][2], q[8][2];
#pragma unroll
    for (int nt = 0; nt < 8; nt++) { s[nt][0] = s[nt][1] = q[nt][0] = q[nt][1] = 0.f; }

#pragma unroll 1
    for (int t = 0; t < TILES_PER_CTA; t++) {
        float* cur = (t & 1) ? sHb : sHa;
        float* nxt = (t & 1) ? sHa : sHb;
        if (t < TILES_PER_CTA - 1) {
            issue_tile(t + 1, nxt);
            asm volatile("cp.async.wait_group 1;\n" ::);
        } else {
            asm volatile("cp.async.wait_group 0;\n" ::);
        }
        __syncthreads();

        float acc[2][8][4];
#pragma unroll
        for (int mt = 0; mt < 2; mt++)
#pragma unroll
            for (int nt = 0; nt < 8; nt++)
#pragma unroll
                for (int i = 0; i < 4; i++) acc[mt][nt][i] = 0.f;

#pragma unroll
        for (int kk = 0; kk < 8; kk++) {
            const int k0 = kk * 8;
            uint32_t a[2][4];
#pragma unroll
            for (int mt = 0; mt < 2; mt++) {
                int rb = mrow + mt * 16;
                a[mt][0] = __float_as_uint(cur[(rb + g    ) * SHS + k0 + tg    ]);
                a[mt][1] = __float_as_uint(cur[(rb + g + 8) * SHS + k0 + tg    ]);
                a[mt][2] = __float_as_uint(cur[(rb + g    ) * SHS + k0 + tg + 4]);
                a[mt][3] = __float_as_uint(cur[(rb + g + 8) * SHS + k0 + tg + 4]);
            }
#pragma unroll
            for (int nt = 0; nt < 8; nt++) {
                uint32_t b0 = __float_as_uint(sW[(k0 + tg    ) * SHS + nt * 8 + g]);
                uint32_t b1 = __float_as_uint(sW[(k0 + tg + 4) * SHS + nt * 8 + g]);
#pragma unroll
                for (int mt = 0; mt < 2; mt++) {
                    asm volatile(
                        "mma.sync.aligned.m16n8k8.row.col.f32.tf32.tf32.f32 "
                        "{%0,%1,%2,%3}, {%4,%5,%6,%7}, {%8,%9}, {%0,%1,%2,%3};"
                        : "+f"(acc[mt][nt][0]), "+f"(acc[mt][nt][1]),
                          "+f"(acc[mt][nt][2]), "+f"(acc[mt][nt][3])
                        : "r"(a[mt][0]), "r"(a[mt][1]), "r"(a[mt][2]), "r"(a[mt][3]),
                          "r"(b0), "r"(b1));
                }
            }
        }

        // Epilogue: fp16 store + stat accumulation in registers
        __half* outp = g_Htp + ((size_t)blockIdx.x * ROWS_PER_CTA + (size_t)t * 128) * F;
#pragma unroll
        for (int mt = 0; mt < 2; mt++) {
            int rb = mrow + mt * 16;
#pragma unroll
            for (int nt = 0; nt < 8; nt++) {
                int colb = nt * 8 + 2 * tg;
                float a0 = acc[mt][nt][0], a1 = acc[mt][nt][1];
                float a2 = acc[mt][nt][2], a3 = acc[mt][nt][3];
                *(__half2*)&outp[(size_t)(rb + g    ) * F + colb] = __floats2half2_rn(a0, a1);
                *(__half2*)&outp[(size_t)(rb + g + 8) * F + colb] = __floats2half2_rn(a2, a3);
                s[nt][0] += a0 + a2;           s[nt][1] += a1 + a3;
                q[nt][0] += a0 * a0 + a2 * a2; q[nt][1] += a1 * a1 + a3 * a3;
            }
        }
        __syncthreads();   // all warps done reading `cur` before it is refilled
    }

    // Reduce stats: butterfly over g, combine warps in smem, 64 global atomics
#pragma unroll
    for (int off = 4; off < 32; off <<= 1) {
#pragma unroll
        for (int nt = 0; nt < 8; nt++) {
            s[nt][0] += __shfl_xor_sync(0xffffffffu, s[nt][0], off);
            s[nt][1] += __shfl_xor_sync(0xffffffffu, s[nt][1], off);
            q[nt][0] += __shfl_xor_sync(0xffffffffu, q[nt][0], off);
            q[nt][1] += __shfl_xor_sync(0xffffffffu, q[nt][1], off);
        }
    }
    if (lane < 4) {
#pragma unroll
        for (int nt = 0; nt < 8; nt++) {
            int c = nt * 8 + 2 * lane;
            atomicAdd(&sSum[c],     s[nt][0]);
            atomicAdd(&sSum[c + 1], s[nt][1]);
            atomicAdd(&sSq[c],      q[nt][0]);
            atomicAdd(&sSq[c + 1],  q[nt][1]);
        }
    }
    __syncthreads();
    if (tid < F) {
        atomicAdd(&g_sum[tid],   sSum[tid]);
        atomicAdd(&g_sumsq[tid], sSq[tid]);
    }
}

// ---------------- K2: finalize BN scale/bias ---------------------------------
__global__ void k_stats(const float* __restrict__ gamma, const float* __restrict__ beta) {
    int o = threadIdx.x;
    if (o < F) {
        float inv_m = 1.f / (float)M_TOTAL;
        float mean = g_sum[o] * inv_m;
        float var  = g_sumsq[o] * inv_m - mean * mean;
        float is   = rsqrtf(var + 1e-5f);
        float sc   = gamma[o] * is;
        g_scale[o] = sc;
        g_bias[o]  = beta[o] - mean * sc;
    }
}

// ---------------- K3: BN + ReLU + normalized 3x3 stencil (fp16 in) -----------
// CTA: 288 threads = 18 cols (16 out + 2 halo) x 16 half4 chunks.
// 2 output rows per __syncthreads (4 smem buffers), loads prefetched 2 ahead.
__global__ __launch_bounds__(288, 4)
void k_stencil(float* __restrict__ out) {
    __shared__ float4 cs[4][18][16];

    const int tid   = threadIdx.x;
    const int chunk = tid & 15;      // 0..15 (4 channels each)
    const int colL  = tid >> 4;      // 0..17
    const int b     = blockIdx.z;
    const int j0    = blockIdx.x * 16;
    const int i0    = blockIdx.y * 32;
    const int j     = j0 - 1 + colL;
    const bool jin  = (j >= 0 && j < CDIM);
    const bool isOut = (colL >= 1 && colL <= 16);

    const float4 sc = *(const float4*)&g_scale[chunk * 4];
    const float4 bs = *(const float4*)&g_bias[chunk * 4];
    const __half* base = g_Htp + (size_t)b * NPIX * F;

    auto rawload = [&](int i) -> uint2 {
        if (!jin || i < 0 || i >= RDIM) return make_uint2(0u, 0u);
        return *(const uint2*)&base[((size_t)i * CDIM + j) * F + chunk * 4];
    };
    auto bnrow = [&](uint2 rw, int i) -> float4 {
        if (!jin || i < 0 || i >= RDIM) return make_float4(0.f, 0.f, 0.f, 0.f);
        float2 f0 = __half22float2(*(__half2*)&rw.x);
        float2 f1 = __half22float2(*(__half2*)&rw.y);
        float d = dval(i, j);
        float4 r;
        r.x = fmaxf(fmaf(f0.x, sc.x, bs.x), 0.f) * d;
        r.y = fmaxf(fmaf(f0.y, sc.y, bs.y), 0.f) * d;
        r.z = fmaxf(fmaf(f1.x, sc.z, bs.z), 0.f) * d;
        r.w = fmaxf(fmaf(f1.y, sc.w, bs.w), 0.f) * d;
        return r;
    };

    float4 p = bnrow(rawload(i0 - 1), i0 - 1);
    float4 c = bnrow(rawload(i0), i0);
    uint2 rn  = rawload(i0 + 1);
    uint2 rn2 = rawload(i0 + 2);
    int bb = 0;

    for (int r = 0; r < 16; r++) {
        const int i = i0 + 2 * r;
        uint2 rn3 = rawload(i + 3);
        uint2 rn4 = rawload(i + 4);
        float4 n  = bnrow(rn,  i + 1);
        float4 n2 = bnrow(rn2, i + 2);
        float4 v0, v1;
        v0.x = p.x + c.x + n.x;   v1.x = c.x + n.x + n2.x;
        v0.y = p.y + c.y + n.y;   v1.y = c.y + n.y + n2.y;
        v0.z = p.z + c.z + n.z;   v1.z = c.z + n.z + n2.z;
        v0.w = p.w + c.w + n.w;   v1.w = c.w + n.w + n2.w;
        cs[bb][colL][chunk]     = v0;
        cs[bb + 1][colL][chunk] = v1;
        __syncthreads();
        if (isOut) {
            float4 l0 = cs[bb][colL - 1][chunk];
            float4 r0 = cs[bb][colL + 1][chunk];
            float dc0 = dval(i, j);
            float4 o0;
            o0.x = (l0.x + v0.x + r0.x) * dc0;
            o0.y = (l0.y + v0.y + r0.y) * dc0;
            o0.z = (l0.z + v0.z + r0.z) * dc0;
            o0.w = (l0.w + v0.w + r0.w) * dc0;
            *(float4*)&out[((size_t)b * NPIX + (size_t)i * CDIM + j) * F + chunk * 4] = o0;

            float4 l1 = cs[bb + 1][colL - 1][chunk];
            float4 r1 = cs[bb + 1][colL + 1][chunk];
            float dc1 = dval(i + 1, j);
            float4 o1;
            o1.x = (l1.x + v1.x + r1.x) * dc1;
            o1.y = (l1.y + v1.y + r1.y) * dc1;
            o1.z = (l1.z + v1.z + r1.z) * dc1;
            o1.w = (l1.w + v1.w + r1.w) * dc1;
            *(float4*)&out[((size_t)b * NPIX + (size_t)(i + 1) * CDIM + j) * F + chunk * 4] = o1;
        }
        p = n; c = n2; rn = rn3; rn2 = rn4; bb ^= 2;
    }
}

// ---------------- launch ------------------------------------------------------
extern "C" void kernel_launch(void* const* d_in, const int* in_sizes, int n_in,
                              void* d_out, int out_size) {
    (void)in_sizes; (void)n_in; (void)out_size;
    const float* H     = (const float*)d_in[0];
    const float* W     = (const float*)d_in[1];
    const float* gamma = (const float*)d_in[2];
    const float* beta  = (const float*)d_in[3];
    float* out = (float*)d_out;

    const int smemK1 = (64 * SHS + 2 * 128 * SHS + 2 * F) * sizeof(float);  // ~87.5KB
    cudaFuncSetAttribute(k_gemm, cudaFuncAttributeMaxDynamicSharedMemorySize, smemK1);

    k_zero<<<1, 64>>>();
    k_gemm<<<M_TOTAL / ROWS_PER_CTA, 128, smemK1>>>(H, W);
    k_stats<<<1, 64>>>(gamma, beta);
    dim3 g3(CDIM / 16, RDIM / 32, BATCH);
    k_stencil<<<g3, 288>>>(out);
}